// round 1
// baseline (speedup 1.0000x reference)
#include <cuda_runtime.h>
#include <cstdint>
#include <cstddef>

// ---------------------------------------------------------------------------
// myModel_68796786147565: 2-layer GraphSAGE mean-aggregator + segment sum +
// SELU readout MLP.
//
// Shapes (fixed by the dataset):
//   h0 (10000,64)  h1 (100000,64)  h2 (2500000,64)
//   w0 (128,128) b0(128)  w1 (256,128) b1(128)
//   wr1 (128,35) wr2 (35,35) wr3 (35,1)  gids (10000,) sorted in [0,64)
// Output: (64,1) fp32.
//
// Pipeline:
//   m2   = group_mean(h2, 25)                      (100000,64)
//   m1   = group_mean(h1, 10)                      (10000,64)
//   a12  = relu([h1|m2] @ w0 + b0)                 (100000,128)
//   a01  = relu([h0|m1] @ w0 + b0)                 (10000,128)
//   ma12 = group_mean(a12, 10)                     (10000,128)
//   out  = relu([a01|ma12] @ w1 + b1)  --atomic--> seg (64,128)
//   r    = (selu(selu(seg@wr1+br1)@wr2+br2))@wr3+br3   -> d_out (64)
// ---------------------------------------------------------------------------

static constexpr int NN   = 10000;
static constexpr int R1   = 100000;
static constexpr int DIM  = 64;
static constexpr int OUT  = 128;
static constexpr int G    = 64;

// Scratch (device globals; no runtime allocation allowed)
__device__ float g_m2  [R1 * DIM];      // 25.6 MB
__device__ float g_m1  [NN * DIM];      //  2.6 MB
__device__ float g_a12 [R1 * OUT];      // 51.2 MB
__device__ float g_a01 [NN * OUT];      //  5.1 MB
__device__ float g_ma12[NN * OUT];      //  5.1 MB
__device__ float g_seg [G * OUT];       //   32 KB

// ---------------------------------------------------------------------------
__global__ void zero_seg_kernel() {
    int i = blockIdx.x * blockDim.x + threadIdx.x;
    if (i < G * OUT) g_seg[i] = 0.0f;
}

// ---------------------------------------------------------------------------
// Group mean: one warp per group of GRP consecutive rows of width D.
// Each lane owns D/32 consecutive floats (float2 for D=64, float4 for D=128).
// Fully coalesced: one warp-row read = D*4 contiguous bytes.
// ---------------------------------------------------------------------------
template <int D, int GRP>
__global__ void group_mean_kernel(const float* __restrict__ src,
                                  float* __restrict__ dst, int ngroups) {
    constexpr int VEC = D / 32;
    int w    = (int)((blockIdx.x * blockDim.x + threadIdx.x) >> 5);
    int lane = threadIdx.x & 31;
    if (w >= ngroups) return;

    const float* base = src + (size_t)w * GRP * D + lane * VEC;
    float acc[VEC];
#pragma unroll
    for (int v = 0; v < VEC; v++) acc[v] = 0.0f;

#pragma unroll
    for (int r = 0; r < GRP; r++) {
        if (VEC == 2) {
            float2 t = *(const float2*)(base + (size_t)r * D);
            acc[0] += t.x; acc[1] += t.y;
        } else {
            float4 t = *(const float4*)(base + (size_t)r * D);
            acc[0] += t.x; acc[1] += t.y; acc[2] += t.z; acc[3] += t.w;
        }
    }
    const float inv = 1.0f / (float)GRP;
    float* o = dst + (size_t)w * D + lane * VEC;
    if (VEC == 2) {
        *(float2*)o = make_float2(acc[0] * inv, acc[1] * inv);
    } else {
        *(float4*)o = make_float4(acc[0] * inv, acc[1] * inv,
                                  acc[2] * inv, acc[3] * inv);
    }
}

// ---------------------------------------------------------------------------
// SAGE GEMM: out[row] = relu(concat(A[row] (KA), B[row] (KB)) @ W + bias)
// W is (K,128) row-major, resident in SMEM. Block = 256 threads, 64 rows.
// Thread (tx,ty): 4 rows x 8 cols micro-tile -> 32 FMA per k-step vs 6 LDS.
// X tile padded by 4 floats/row to avoid smem bank conflicts on the x loads.
// If SEG: fused segment-sum via atomicAdd into seg[gids[row]][col].
// ---------------------------------------------------------------------------
template <int KA, int KB, bool SEG>
__global__ void __launch_bounds__(256)
sage_gemm_kernel(const float* __restrict__ A, const float* __restrict__ B,
                 const float* __restrict__ W, const float* __restrict__ bias,
                 float* __restrict__ out, int nrows,
                 const int* __restrict__ gids, float* __restrict__ seg) {
    constexpr int K  = KA + KB;
    constexpr int KP = K + 4;   // padded X row stride (floats)

    extern __shared__ float smem[];
    float* Xs = smem;             // 64 * KP
    float* Ws = smem + 64 * KP;   // K * 128

    const int tid     = threadIdx.x;
    const int rowBase = blockIdx.x * 64;

    // --- load 64 x K X-tile (first KA cols from A, rest from B) ---
    constexpr int NX4 = 64 * K / 4;
    for (int i = tid; i < NX4; i += 256) {
        int r = i / (K / 4);
        int c = (i % (K / 4)) * 4;
        int row = rowBase + r;
        float4 v = make_float4(0.f, 0.f, 0.f, 0.f);
        if (row < nrows) {
            if (c < KA) v = *(const float4*)(A + (size_t)row * KA + c);
            else        v = *(const float4*)(B + (size_t)row * KB + (c - KA));
        }
        *(float4*)(Xs + r * KP + c) = v;
    }
    // --- load W (K x 128) ---
    constexpr int NW4 = K * 128 / 4;
    for (int i = tid; i < NW4; i += 256) {
        *(float4*)(Ws + i * 4) = *(const float4*)(W + i * 4);
    }
    __syncthreads();

    const int tx = tid & 15;   // 16 col-groups of 8 cols
    const int ty = tid >> 4;   // 16 row-groups of 4 rows

    float acc[4][8];
#pragma unroll
    for (int i = 0; i < 4; i++)
#pragma unroll
        for (int j = 0; j < 8; j++) acc[i][j] = 0.0f;

    const float* Xp = Xs + ty * 4 * KP;
    const float* Wp = Ws + tx * 8;

#pragma unroll 8
    for (int k = 0; k < K; k++) {
        float4 wa = *(const float4*)(Wp + k * 128);
        float4 wb = *(const float4*)(Wp + k * 128 + 4);
        float wv[8] = {wa.x, wa.y, wa.z, wa.w, wb.x, wb.y, wb.z, wb.w};
        float xv[4];
        xv[0] = Xp[k];
        xv[1] = Xp[KP + k];
        xv[2] = Xp[2 * KP + k];
        xv[3] = Xp[3 * KP + k];
#pragma unroll
        for (int i = 0; i < 4; i++)
#pragma unroll
            for (int j = 0; j < 8; j++)
                acc[i][j] = fmaf(xv[i], wv[j], acc[i][j]);
    }

    // --- epilogue: bias + relu + store (+ fused segment atomicAdd) ---
    float bv[8];
#pragma unroll
    for (int j = 0; j < 8; j++) bv[j] = __ldg(bias + tx * 8 + j);

#pragma unroll
    for (int i = 0; i < 4; i++) {
        int row = rowBase + ty * 4 + i;
        if (row >= nrows) continue;
        float v[8];
#pragma unroll
        for (int j = 0; j < 8; j++) {
            float t = acc[i][j] + bv[j];
            v[j] = t > 0.0f ? t : 0.0f;
        }
        if (out != nullptr) {
            float4* op = (float4*)(out + (size_t)row * 128 + tx * 8);
            op[0] = make_float4(v[0], v[1], v[2], v[3]);
            op[1] = make_float4(v[4], v[5], v[6], v[7]);
        }
        if (SEG) {
            int g = gids[row];
            float* sp = seg + g * 128 + tx * 8;
#pragma unroll
            for (int j = 0; j < 8; j++) atomicAdd(sp + j, v[j]);
        }
    }
}

// ---------------------------------------------------------------------------
// Readout: r = selu(selu(seg@wr1+br1)@wr2+br2)@wr3+br3, one thread per graph.
// ---------------------------------------------------------------------------
__global__ void readout_kernel(const float* __restrict__ seg,
                               const float* __restrict__ wr1, const float* __restrict__ br1,
                               const float* __restrict__ wr2, const float* __restrict__ br2,
                               const float* __restrict__ wr3, const float* __restrict__ br3,
                               float* __restrict__ outp) {
    __shared__ float w1s[128 * 35];
    __shared__ float w2s[35 * 35];
    __shared__ float w3s[35], b1s[35], b2s[35];
    __shared__ float b3s;

    int tid = threadIdx.x;
    for (int i = tid; i < 128 * 35; i += blockDim.x) w1s[i] = wr1[i];
    for (int i = tid; i < 35 * 35;  i += blockDim.x) w2s[i] = wr2[i];
    if (tid < 35) { w3s[tid] = wr3[tid]; b1s[tid] = br1[tid]; b2s[tid] = br2[tid]; }
    if (tid == 0) b3s = br3[0];
    __syncthreads();

    if (tid >= G) return;

    const float SC = 1.0507009873554805f;
    const float AL = 1.6732632423543772f;

    const float* s = seg + tid * 128;
    float r1[35];
#pragma unroll
    for (int j = 0; j < 35; j++) r1[j] = b1s[j];
    for (int k = 0; k < 128; k++) {
        float x = s[k];
#pragma unroll
        for (int j = 0; j < 35; j++) r1[j] = fmaf(x, w1s[k * 35 + j], r1[j]);
    }
#pragma unroll
    for (int j = 0; j < 35; j++) {
        float x = r1[j];
        r1[j] = SC * (x > 0.0f ? x : AL * (expf(x) - 1.0f));
    }

    float r2[35];
#pragma unroll
    for (int j = 0; j < 35; j++) r2[j] = b2s[j];
#pragma unroll
    for (int k = 0; k < 35; k++) {
        float x = r1[k];
#pragma unroll
        for (int j = 0; j < 35; j++) r2[j] = fmaf(x, w2s[k * 35 + j], r2[j]);
    }
#pragma unroll
    for (int j = 0; j < 35; j++) {
        float x = r2[j];
        r2[j] = SC * (x > 0.0f ? x : AL * (expf(x) - 1.0f));
    }

    float r3 = b3s;
#pragma unroll
    for (int j = 0; j < 35; j++) r3 = fmaf(r2[j], w3s[j], r3);
    outp[tid] = r3;
}

// ---------------------------------------------------------------------------
extern "C" void kernel_launch(void* const* d_in, const int* in_sizes, int n_in,
                              void* d_out, int out_size) {
    const float* h0  = (const float*)d_in[0];
    const float* h1  = (const float*)d_in[1];
    const float* h2  = (const float*)d_in[2];
    const float* w0  = (const float*)d_in[3];
    const float* b0  = (const float*)d_in[4];
    const float* w1  = (const float*)d_in[5];
    const float* b1  = (const float*)d_in[6];
    const float* wr1 = (const float*)d_in[7];
    const float* br1 = (const float*)d_in[8];
    const float* wr2 = (const float*)d_in[9];
    const float* br2 = (const float*)d_in[10];
    const float* wr3 = (const float*)d_in[11];
    const float* br3 = (const float*)d_in[12];
    const int*   gid = (const int*)d_in[13];

    const int n  = in_sizes[0] / DIM;   // 10000
    const int r1 = in_sizes[1] / DIM;   // 100000

    float *m2, *m1, *a12, *a01, *ma12, *seg;
    cudaGetSymbolAddress((void**)&m2,   g_m2);
    cudaGetSymbolAddress((void**)&m1,   g_m1);
    cudaGetSymbolAddress((void**)&a12,  g_a12);
    cudaGetSymbolAddress((void**)&a01,  g_a01);
    cudaGetSymbolAddress((void**)&ma12, g_ma12);
    cudaGetSymbolAddress((void**)&seg,  g_seg);

    constexpr int SMEM_K128 = (64 * (128 + 4) + 128 * 128) * 4;  // ~97 KB
    constexpr int SMEM_K256 = (64 * (256 + 4) + 256 * 128) * 4;  // ~193 KB
    cudaFuncSetAttribute((const void*)sage_gemm_kernel<64, 64, false>,
                         cudaFuncAttributeMaxDynamicSharedMemorySize, SMEM_K128);
    cudaFuncSetAttribute((const void*)sage_gemm_kernel<128, 128, true>,
                         cudaFuncAttributeMaxDynamicSharedMemorySize, SMEM_K256);

    zero_seg_kernel<<<32, 256>>>();

    // group means (h2 -> m2 dominates: 640 MB HBM read)
    group_mean_kernel<64, 25><<<(r1 + 7) / 8, 256>>>(h2, m2, r1);
    group_mean_kernel<64, 10><<<(n + 7) / 8, 256>>>(h1, m1, n);

    // round-0 aggregations (shared w0)
    sage_gemm_kernel<64, 64, false><<<(r1 + 63) / 64, 256, SMEM_K128>>>(
        h1, m2, w0, b0, a12, r1, nullptr, nullptr);
    sage_gemm_kernel<64, 64, false><<<(n + 63) / 64, 256, SMEM_K128>>>(
        h0, m1, w0, b0, a01, n, nullptr, nullptr);

    // mean of a12 groups
    group_mean_kernel<128, 10><<<(n + 7) / 8, 256>>>(a12, ma12, n);

    // round-1 aggregation with fused segment-sum
    sage_gemm_kernel<128, 128, true><<<(n + 63) / 64, 256, SMEM_K256>>>(
        a01, ma12, w1, b1, nullptr, n, gid, seg);

    // readout MLP
    readout_kernel<<<1, 128>>>(seg, wr1, br1, wr2, br2, wr3, br3, (float*)d_out);
}

// round 2
// speedup vs baseline: 1.1116x; 1.1116x over previous
#include <cuda_runtime.h>
#include <cstdint>
#include <cstddef>

// ---------------------------------------------------------------------------
// 2-layer GraphSAGE mean-aggregator + segment sum + SELU readout.
//
// Fused pipeline (R2):
//   K1 : ma12 = groupmean10( relu([h1 | groupmean25(h2)] @ w0 + b0) )
//        - h2 mean computed on the fly in the prologue (640MB stream)
//        - a12 never hits HBM; 80-row tiles = exactly 8 mean-groups
//   K2a: a01 = relu([h0 | groupmean10(h1)] @ w0 + b0)
//   K2b: seg += relu([a01 | ma12] @ w1 + b1)  (fused segment atomicAdd)
//   K3 : r = selu(selu(seg@wr1+br1)@wr2+br2)@wr3+br3
//
// GEMM core: fp32, packed fma.rn.f32x2 (FFMA2), 4 rows x 8 cols / thread,
// W pairs loaded as ulonglong2 (bit-identical float pairs), X as float4/4k.
// ---------------------------------------------------------------------------

static constexpr int NN  = 10000;
static constexpr int DIM = 64;
static constexpr int G   = 64;

__device__ float g_ma12[NN * 128];   // 5.1 MB
__device__ float g_a01 [NN * 128];   // 5.1 MB
__device__ float g_seg [G * 128];    //  32 KB

// ---------------------------------------------------------------------------
__global__ void zero_seg_kernel() {
    int i = blockIdx.x * blockDim.x + threadIdx.x;
    if (i < G * 128) g_seg[i] = 0.0f;
}

__device__ __forceinline__ void unpack2(unsigned long long v, float& lo, float& hi) {
    asm("mov.b64 {%0, %1}, %2;" : "=f"(lo), "=f"(hi) : "l"(v));
}

// ---------------------------------------------------------------------------
// GEMM core: acc[4 rows][4 col-pairs] (f32x2) over K, Xs row stride KP,
// Ws row-major (K x 128). Thread (tx in [0,16), ty): rows ty*4.., cols tx*8..
// ---------------------------------------------------------------------------
template <int K, int KP>
__device__ __forceinline__ void gemm_core(const float* __restrict__ Xs,
                                          const float* __restrict__ Ws,
                                          int tx, int ty,
                                          unsigned long long acc2[4][4]) {
#pragma unroll
    for (int r = 0; r < 4; r++)
#pragma unroll
        for (int p = 0; p < 4; p++) acc2[r][p] = 0ULL;

    const float* Xp = Xs + ty * 4 * KP;
    const float* Wp = Ws + tx * 8;

#pragma unroll 4
    for (int k = 0; k < K; k += 4) {
        float x4[4][4];
#pragma unroll
        for (int r = 0; r < 4; r++) {
            float4 t = *(const float4*)(Xp + r * KP + k);
            x4[r][0] = t.x; x4[r][1] = t.y; x4[r][2] = t.z; x4[r][3] = t.w;
        }
#pragma unroll
        for (int kk = 0; kk < 4; kk++) {
            const float* wrow = Wp + (k + kk) * 128;
            ulonglong2 wlo = *(const ulonglong2*)(wrow);
            ulonglong2 whi = *(const ulonglong2*)(wrow + 4);
            unsigned long long wp0 = wlo.x, wp1 = wlo.y;
            unsigned long long wp2 = whi.x, wp3 = whi.y;
#pragma unroll
            for (int r = 0; r < 4; r++) {
                unsigned long long xx;
                asm("mov.b64 %0, {%1, %1};" : "=l"(xx) : "f"(x4[r][kk]));
                asm("fma.rn.f32x2 %0, %1, %2, %3;"
                    : "=l"(acc2[r][0]) : "l"(xx), "l"(wp0), "l"(acc2[r][0]));
                asm("fma.rn.f32x2 %0, %1, %2, %3;"
                    : "=l"(acc2[r][1]) : "l"(xx), "l"(wp1), "l"(acc2[r][1]));
                asm("fma.rn.f32x2 %0, %1, %2, %3;"
                    : "=l"(acc2[r][2]) : "l"(xx), "l"(wp2), "l"(acc2[r][2]));
                asm("fma.rn.f32x2 %0, %1, %2, %3;"
                    : "=l"(acc2[r][3]) : "l"(xx), "l"(wp3), "l"(acc2[r][3]));
            }
        }
    }
}

// ---------------------------------------------------------------------------
// K1: 80 rows/block (8 mean-groups), 320 threads. Grid = 1250 (exact).
// smem: Xs 80x132 + Ws 128x128 = 107776 B -> 2 CTAs/SM.
// ---------------------------------------------------------------------------
__global__ void __launch_bounds__(320)
k1_fused(const float* __restrict__ h1, const float* __restrict__ h2,
         const float* __restrict__ w0, const float* __restrict__ b0,
         float* __restrict__ ma12) {
    extern __shared__ float smem[];
    float* Xs = smem;               // 80 * 132
    float* Ws = smem + 80 * 132;    // 128 * 128

    const int tid = threadIdx.x;
    const int rb  = blockIdx.x * 80;

    // h1 tile -> Xs[:, 0:64]
    for (int i = tid; i < 80 * 16; i += 320) {
        int r = i >> 4, c = (i & 15) << 2;
        *(float4*)(Xs + r * 132 + c) =
            *(const float4*)(h1 + (size_t)(rb + r) * 64 + c);
    }
    // mean25(h2) on the fly -> Xs[:, 64:128]
    for (int i = tid; i < 80 * 16; i += 320) {
        int r = i >> 4, c = (i & 15) << 2;
        const float4* p =
            (const float4*)(h2 + (size_t)(rb + r) * 25 * 64 + c);
        float4 a = make_float4(0.f, 0.f, 0.f, 0.f);
#pragma unroll
        for (int j = 0; j < 25; j++) {
            float4 t = p[j * 16];
            a.x += t.x; a.y += t.y; a.z += t.z; a.w += t.w;
        }
        *(float4*)(Xs + r * 132 + 64 + c) =
            make_float4(a.x * 0.04f, a.y * 0.04f, a.z * 0.04f, a.w * 0.04f);
    }
    // w0 -> Ws
    for (int i = tid; i < 128 * 32; i += 320) {
        *(float4*)(Ws + i * 4) = *(const float4*)(w0 + i * 4);
    }
    __syncthreads();

    const int tx = tid & 15, ty = tid >> 4;
    unsigned long long acc2[4][4];
    gemm_core<128, 132>(Xs, Ws, tx, ty, acc2);

    float bv[8];
#pragma unroll
    for (int j = 0; j < 8; j++) bv[j] = b0[tx * 8 + j];

    __syncthreads();   // all reads of Xs done; reuse it for the relu tile
#pragma unroll
    for (int r = 0; r < 4; r++) {
        float v[8];
#pragma unroll
        for (int p = 0; p < 4; p++) unpack2(acc2[r][p], v[2 * p], v[2 * p + 1]);
#pragma unroll
        for (int j = 0; j < 8; j++) {
            float t = v[j] + bv[j];
            v[j] = t > 0.0f ? t : 0.0f;
        }
        float* dr = Xs + (ty * 4 + r) * 132 + tx * 8;
        *(float4*)(dr)     = make_float4(v[0], v[1], v[2], v[3]);
        *(float4*)(dr + 4) = make_float4(v[4], v[5], v[6], v[7]);
    }
    __syncthreads();

    // group mean of 10 -> ma12 (8 groups x 128 cols per block)
    for (int o = tid; o < 1024; o += 320) {
        int gl = o >> 7, c = o & 127;
        float s = 0.0f;
#pragma unroll
        for (int r2 = 0; r2 < 10; r2++) s += Xs[(gl * 10 + r2) * 132 + c];
        ma12[(size_t)(blockIdx.x * 8 + gl) * 128 + c] = s * 0.1f;
    }
}

// ---------------------------------------------------------------------------
// K2a: a01 = relu([h0 | mean10(h1)] @ w0 + b0). 64 rows/block, 256 threads.
// ---------------------------------------------------------------------------
__global__ void __launch_bounds__(256)
k2a_fused(const float* __restrict__ h0, const float* __restrict__ h1,
          const float* __restrict__ w0, const float* __restrict__ b0,
          float* __restrict__ a01, int n) {
    extern __shared__ float smem[];
    float* Xs = smem;               // 64 * 132
    float* Ws = smem + 64 * 132;    // 128 * 128

    const int tid = threadIdx.x;
    const int rb  = blockIdx.x * 64;

    for (int i = tid; i < 64 * 16; i += 256) {
        int r = i >> 4, c = (i & 15) << 2;
        int row = rb + r;
        float4 v = make_float4(0.f, 0.f, 0.f, 0.f);
        if (row < n) v = *(const float4*)(h0 + (size_t)row * 64 + c);
        *(float4*)(Xs + r * 132 + c) = v;
    }
    for (int i = tid; i < 64 * 16; i += 256) {
        int r = i >> 4, c = (i & 15) << 2;
        int row = rb + r;
        float4 a = make_float4(0.f, 0.f, 0.f, 0.f);
        if (row < n) {
            const float4* p = (const float4*)(h1 + (size_t)row * 10 * 64 + c);
#pragma unroll
            for (int j = 0; j < 10; j++) {
                float4 t = p[j * 16];
                a.x += t.x; a.y += t.y; a.z += t.z; a.w += t.w;
            }
            a.x *= 0.1f; a.y *= 0.1f; a.z *= 0.1f; a.w *= 0.1f;
        }
        *(float4*)(Xs + r * 132 + 64 + c) = a;
    }
    for (int i = tid; i < 128 * 32; i += 256) {
        *(float4*)(Ws + i * 4) = *(const float4*)(w0 + i * 4);
    }
    __syncthreads();

    const int tx = tid & 15, ty = tid >> 4;
    unsigned long long acc2[4][4];
    gemm_core<128, 132>(Xs, Ws, tx, ty, acc2);

    float bv[8];
#pragma unroll
    for (int j = 0; j < 8; j++) bv[j] = b0[tx * 8 + j];

#pragma unroll
    for (int r = 0; r < 4; r++) {
        int row = rb + ty * 4 + r;
        if (row >= n) continue;
        float v[8];
#pragma unroll
        for (int p = 0; p < 4; p++) unpack2(acc2[r][p], v[2 * p], v[2 * p + 1]);
#pragma unroll
        for (int j = 0; j < 8; j++) {
            float t = v[j] + bv[j];
            v[j] = t > 0.0f ? t : 0.0f;
        }
        float* dr = a01 + (size_t)row * 128 + tx * 8;
        *(float4*)(dr)     = make_float4(v[0], v[1], v[2], v[3]);
        *(float4*)(dr + 4) = make_float4(v[4], v[5], v[6], v[7]);
    }
}

// ---------------------------------------------------------------------------
// K2b: seg[g] += relu([a01 | ma12] @ w1 + b1). K=256. 64 rows/block.
// smem: Xs 64x260 + Ws 256x128 = 197632 B -> 1 CTA/SM (grid 157 ~ 1 wave).
// ---------------------------------------------------------------------------
__global__ void __launch_bounds__(256)
k2b_fused(const float* __restrict__ a01, const float* __restrict__ ma12,
          const float* __restrict__ w1, const float* __restrict__ b1,
          const int* __restrict__ gid, float* __restrict__ seg, int n) {
    extern __shared__ float smem[];
    float* Xs = smem;               // 64 * 260
    float* Ws = smem + 64 * 260;    // 256 * 128

    const int tid = threadIdx.x;
    const int rb  = blockIdx.x * 64;

    for (int i = tid; i < 64 * 64; i += 256) {
        int r = i >> 6, c = (i & 63) << 2;
        int row = rb + r;
        float4 v = make_float4(0.f, 0.f, 0.f, 0.f);
        if (row < n) {
            if (c < 128) v = *(const float4*)(a01  + (size_t)row * 128 + c);
            else         v = *(const float4*)(ma12 + (size_t)row * 128 + c - 128);
        }
        *(float4*)(Xs + r * 260 + c) = v;
    }
    for (int i = tid; i < 256 * 32; i += 256) {
        *(float4*)(Ws + i * 4) = *(const float4*)(w1 + i * 4);
    }
    __syncthreads();

    const int tx = tid & 15, ty = tid >> 4;
    unsigned long long acc2[4][4];
    gemm_core<256, 260>(Xs, Ws, tx, ty, acc2);

    float bv[8];
#pragma unroll
    for (int j = 0; j < 8; j++) bv[j] = b1[tx * 8 + j];

#pragma unroll
    for (int r = 0; r < 4; r++) {
        int row = rb + ty * 4 + r;
        if (row >= n) continue;
        float v[8];
#pragma unroll
        for (int p = 0; p < 4; p++) unpack2(acc2[r][p], v[2 * p], v[2 * p + 1]);
        int g = gid[row];
        float* sp = seg + (size_t)g * 128 + tx * 8;
#pragma unroll
        for (int j = 0; j < 8; j++) {
            float t = v[j] + bv[j];
            t = t > 0.0f ? t : 0.0f;
            atomicAdd(sp + j, t);
        }
    }
}

// ---------------------------------------------------------------------------
// Readout MLP: one thread per graph.
// ---------------------------------------------------------------------------
__global__ void readout_kernel(const float* __restrict__ seg,
                               const float* __restrict__ wr1, const float* __restrict__ br1,
                               const float* __restrict__ wr2, const float* __restrict__ br2,
                               const float* __restrict__ wr3, const float* __restrict__ br3,
                               float* __restrict__ outp) {
    __shared__ float w1s[128 * 35];
    __shared__ float w2s[35 * 35];
    __shared__ float w3s[35], b1s[35], b2s[35];
    __shared__ float b3s;

    int tid = threadIdx.x;
    for (int i = tid; i < 128 * 35; i += blockDim.x) w1s[i] = wr1[i];
    for (int i = tid; i < 35 * 35;  i += blockDim.x) w2s[i] = wr2[i];
    if (tid < 35) { w3s[tid] = wr3[tid]; b1s[tid] = br1[tid]; b2s[tid] = br2[tid]; }
    if (tid == 0) b3s = br3[0];
    __syncthreads();

    if (tid >= G) return;

    const float SC = 1.0507009873554805f;
    const float AL = 1.6732632423543772f;

    const float* s = seg + tid * 128;
    float r1[35];
#pragma unroll
    for (int j = 0; j < 35; j++) r1[j] = b1s[j];
    for (int k = 0; k < 128; k++) {
        float x = s[k];
#pragma unroll
        for (int j = 0; j < 35; j++) r1[j] = fmaf(x, w1s[k * 35 + j], r1[j]);
    }
#pragma unroll
    for (int j = 0; j < 35; j++) {
        float x = r1[j];
        r1[j] = SC * (x > 0.0f ? x : AL * (expf(x) - 1.0f));
    }

    float r2[35];
#pragma unroll
    for (int j = 0; j < 35; j++) r2[j] = b2s[j];
#pragma unroll
    for (int k = 0; k < 35; k++) {
        float x = r1[k];
#pragma unroll
        for (int j = 0; j < 35; j++) r2[j] = fmaf(x, w2s[k * 35 + j], r2[j]);
    }
#pragma unroll
    for (int j = 0; j < 35; j++) {
        float x = r2[j];
        r2[j] = SC * (x > 0.0f ? x : AL * (expf(x) - 1.0f));
    }

    float r3 = b3s;
#pragma unroll
    for (int j = 0; j < 35; j++) r3 = fmaf(r2[j], w3s[j], r3);
    outp[tid] = r3;
}

// ---------------------------------------------------------------------------
extern "C" void kernel_launch(void* const* d_in, const int* in_sizes, int n_in,
                              void* d_out, int out_size) {
    const float* h0  = (const float*)d_in[0];
    const float* h1  = (const float*)d_in[1];
    const float* h2  = (const float*)d_in[2];
    const float* w0  = (const float*)d_in[3];
    const float* b0  = (const float*)d_in[4];
    const float* w1  = (const float*)d_in[5];
    const float* b1  = (const float*)d_in[6];
    const float* wr1 = (const float*)d_in[7];
    const float* br1 = (const float*)d_in[8];
    const float* wr2 = (const float*)d_in[9];
    const float* br2 = (const float*)d_in[10];
    const float* wr3 = (const float*)d_in[11];
    const float* br3 = (const float*)d_in[12];
    const int*   gid = (const int*)d_in[13];

    const int n  = in_sizes[0] / DIM;   // 10000
    const int r1 = in_sizes[1] / DIM;   // 100000

    float *ma12, *a01, *seg;
    cudaGetSymbolAddress((void**)&ma12, g_ma12);
    cudaGetSymbolAddress((void**)&a01,  g_a01);
    cudaGetSymbolAddress((void**)&seg,  g_seg);

    constexpr int SMEM_K1  = (80 * 132 + 128 * 128) * 4;   // 107776
    constexpr int SMEM_K2A = (64 * 132 + 128 * 128) * 4;   //  99328
    constexpr int SMEM_K2B = (64 * 260 + 256 * 128) * 4;   // 197632
    cudaFuncSetAttribute((const void*)k1_fused,
                         cudaFuncAttributeMaxDynamicSharedMemorySize, SMEM_K1);
    cudaFuncSetAttribute((const void*)k2a_fused,
                         cudaFuncAttributeMaxDynamicSharedMemorySize, SMEM_K2A);
    cudaFuncSetAttribute((const void*)k2b_fused,
                         cudaFuncAttributeMaxDynamicSharedMemorySize, SMEM_K2B);

    zero_seg_kernel<<<32, 256>>>();

    // K1: streams all of h2 (640 MB) once; produces ma12 directly.
    k1_fused<<<r1 / 80, 320, SMEM_K1>>>(h1, h2, w0, b0, ma12);

    // K2a: a01 (reads h0 + h1)
    k2a_fused<<<(n + 63) / 64, 256, SMEM_K2A>>>(h0, h1, w0, b0, a01, n);

    // K2b: round-1 GEMM + fused segment-sum
    k2b_fused<<<(n + 63) / 64, 256, SMEM_K2B>>>(a01, ma12, w1, b1, gid, seg, n);

    // K3: readout
    readout_kernel<<<1, 128>>>(seg, wr1, br1, wr2, br2, wr3, br3, (float*)d_out);
}

// round 3
// speedup vs baseline: 1.5112x; 1.3595x over previous
#include <cuda_runtime.h>
#include <cstdint>
#include <cstddef>

// ---------------------------------------------------------------------------
// 2-layer GraphSAGE mean-aggregator + segment sum + SELU readout.
//
// R3: conflict-free W shared-memory access (thread cols {tx*4, 64+tx*4}),
//     80-row tiles everywhere, single-wave grids for the N=10000 kernels.
//
//   K1 : ma12 = groupmean10( relu([h1 | groupmean25(h2)] @ w0 + b0) )
//   K2a: a01  = relu([h0 | groupmean10(h1)] @ w0 + b0)
//   K2b: seg += relu([a01 | ma12] @ w1 + b1)   (fused segment atomicAdd)
//   K3 : r = selu(selu(seg@wr1+br1)@wr2+br2)@wr3+br3
// ---------------------------------------------------------------------------

static constexpr int NN  = 10000;
static constexpr int DIM = 64;
static constexpr int G   = 64;

__device__ float g_ma12[NN * 128];
__device__ float g_a01 [NN * 128];
__device__ float g_seg [G * 128];

// ---------------------------------------------------------------------------
__global__ void zero_seg_kernel() {
    int i = blockIdx.x * blockDim.x + threadIdx.x;
    if (i < G * 128) g_seg[i] = 0.0f;
}

__device__ __forceinline__ void unpack2(unsigned long long v, float& lo, float& hi) {
    asm("mov.b64 {%0, %1}, %2;" : "=f"(lo), "=f"(hi) : "l"(v));
}

// ---------------------------------------------------------------------------
// GEMM core: 4 rows x 8 cols per thread, cols = {tx*4..+3, 64+tx*4..+3}.
// W loads per k: two LDS.128 over 256B consecutive (conflict-free, 2 phases).
// X loads: one LDS.128 per row per 4k, warp-broadcast (16 lanes same addr).
// Packed fma.rn.f32x2 accumulators.
// ---------------------------------------------------------------------------
template <int K, int KP>
__device__ __forceinline__ void gemm_core(const float* __restrict__ Xs,
                                          const float* __restrict__ Ws,
                                          int tx, int ty,
                                          unsigned long long acc2[4][4]) {
#pragma unroll
    for (int r = 0; r < 4; r++)
#pragma unroll
        for (int p = 0; p < 4; p++) acc2[r][p] = 0ULL;

    const float* Xp  = Xs + ty * 4 * KP;
    const float* WpA = Ws + tx * 4;        // cols tx*4 .. tx*4+3
    const float* WpB = Ws + 64 + tx * 4;   // cols 64+tx*4 .. 64+tx*4+3

#pragma unroll 4
    for (int k = 0; k < K; k += 4) {
        float x4[4][4];
#pragma unroll
        for (int r = 0; r < 4; r++) {
            float4 t = *(const float4*)(Xp + r * KP + k);
            x4[r][0] = t.x; x4[r][1] = t.y; x4[r][2] = t.z; x4[r][3] = t.w;
        }
#pragma unroll
        for (int kk = 0; kk < 4; kk++) {
            ulonglong2 wa = *(const ulonglong2*)(WpA + (k + kk) * 128);
            ulonglong2 wb = *(const ulonglong2*)(WpB + (k + kk) * 128);
#pragma unroll
            for (int r = 0; r < 4; r++) {
                unsigned long long xx;
                asm("mov.b64 %0, {%1, %1};" : "=l"(xx) : "f"(x4[r][kk]));
                asm("fma.rn.f32x2 %0, %1, %2, %3;"
                    : "=l"(acc2[r][0]) : "l"(xx), "l"(wa.x), "l"(acc2[r][0]));
                asm("fma.rn.f32x2 %0, %1, %2, %3;"
                    : "=l"(acc2[r][1]) : "l"(xx), "l"(wa.y), "l"(acc2[r][1]));
                asm("fma.rn.f32x2 %0, %1, %2, %3;"
                    : "=l"(acc2[r][2]) : "l"(xx), "l"(wb.x), "l"(acc2[r][2]));
                asm("fma.rn.f32x2 %0, %1, %2, %3;"
                    : "=l"(acc2[r][3]) : "l"(xx), "l"(wb.y), "l"(acc2[r][3]));
            }
        }
    }
}

// Epilogue helper: unpack acc + bias + relu into v[8] (cols tx*4.., 64+tx*4..)
__device__ __forceinline__ void epi_relu(const unsigned long long acc2r[4],
                                         const float bv[8], float v[8]) {
#pragma unroll
    for (int p = 0; p < 4; p++) unpack2(acc2r[p], v[2 * p], v[2 * p + 1]);
#pragma unroll
    for (int j = 0; j < 8; j++) {
        float t = v[j] + bv[j];
        v[j] = t > 0.0f ? t : 0.0f;
    }
}

// ---------------------------------------------------------------------------
// K1: 80 rows/block (8 mean-groups), 320 threads, grid 1250 (exact).
// smem: Xs 80x132 + Ws 128x128 = 107776 B -> 2 CTAs/SM.
// ---------------------------------------------------------------------------
__global__ void __launch_bounds__(320)
k1_fused(const float* __restrict__ h1, const float* __restrict__ h2,
         const float* __restrict__ w0, const float* __restrict__ b0,
         float* __restrict__ ma12) {
    extern __shared__ float smem[];
    float* Xs = smem;               // 80 * 132
    float* Ws = smem + 80 * 132;    // 128 * 128

    const int tid = threadIdx.x;
    const int rb  = blockIdx.x * 80;

    // h1 tile -> Xs[:, 0:64]
    for (int i = tid; i < 80 * 16; i += 320) {
        int r = i >> 4, c = (i & 15) << 2;
        *(float4*)(Xs + r * 132 + c) =
            *(const float4*)(h1 + (size_t)(rb + r) * 64 + c);
    }
    // mean25(h2) on the fly -> Xs[:, 64:128]  (640MB total stream)
    for (int i = tid; i < 80 * 16; i += 320) {
        int r = i >> 4, c = (i & 15) << 2;
        const float4* p = (const float4*)(h2 + (size_t)(rb + r) * 25 * 64 + c);
        float4 a = make_float4(0.f, 0.f, 0.f, 0.f);
        float4 b = make_float4(0.f, 0.f, 0.f, 0.f);
#pragma unroll
        for (int j = 0; j < 24; j += 2) {
            float4 t = p[j * 16];
            float4 u = p[(j + 1) * 16];
            a.x += t.x; a.y += t.y; a.z += t.z; a.w += t.w;
            b.x += u.x; b.y += u.y; b.z += u.z; b.w += u.w;
        }
        float4 t = p[24 * 16];
        a.x += t.x; a.y += t.y; a.z += t.z; a.w += t.w;
        *(float4*)(Xs + r * 132 + 64 + c) =
            make_float4((a.x + b.x) * 0.04f, (a.y + b.y) * 0.04f,
                        (a.z + b.z) * 0.04f, (a.w + b.w) * 0.04f);
    }
    for (int i = tid; i < 128 * 32; i += 320) {
        *(float4*)(Ws + i * 4) = *(const float4*)(w0 + i * 4);
    }
    __syncthreads();

    const int tx = tid & 15, ty = tid >> 4;
    unsigned long long acc2[4][4];
    gemm_core<128, 132>(Xs, Ws, tx, ty, acc2);

    float bv[8];
#pragma unroll
    for (int j = 0; j < 4; j++) { bv[j] = b0[tx * 4 + j]; bv[4 + j] = b0[64 + tx * 4 + j]; }

    __syncthreads();   // Xs reads done; reuse for relu tile
#pragma unroll
    for (int r = 0; r < 4; r++) {
        float v[8];
        epi_relu(acc2[r], bv, v);
        float* dr = Xs + (ty * 4 + r) * 132;
        *(float4*)(dr + tx * 4)      = make_float4(v[0], v[1], v[2], v[3]);
        *(float4*)(dr + 64 + tx * 4) = make_float4(v[4], v[5], v[6], v[7]);
    }
    __syncthreads();

    // group mean of 10 -> ma12 (8 groups x 128 cols per block)
    for (int o = tid; o < 1024; o += 320) {
        int gl = o >> 7, c = o & 127;
        float s = 0.0f;
#pragma unroll
        for (int r2 = 0; r2 < 10; r2++) s += Xs[(gl * 10 + r2) * 132 + c];
        ma12[(size_t)(blockIdx.x * 8 + gl) * 128 + c] = s * 0.1f;
    }
}

// ---------------------------------------------------------------------------
// K2a: a01 = relu([h0 | mean10(h1)] @ w0 + b0). 80 rows/block, 320 threads.
// ---------------------------------------------------------------------------
__global__ void __launch_bounds__(320)
k2a_fused(const float* __restrict__ h0, const float* __restrict__ h1,
          const float* __restrict__ w0, const float* __restrict__ b0,
          float* __restrict__ a01, int n) {
    extern __shared__ float smem[];
    float* Xs = smem;               // 80 * 132
    float* Ws = smem + 80 * 132;    // 128 * 128

    const int tid = threadIdx.x;
    const int rb  = blockIdx.x * 80;

    for (int i = tid; i < 80 * 16; i += 320) {
        int r = i >> 4, c = (i & 15) << 2;
        int row = rb + r;
        float4 v = make_float4(0.f, 0.f, 0.f, 0.f);
        if (row < n) v = *(const float4*)(h0 + (size_t)row * 64 + c);
        *(float4*)(Xs + r * 132 + c) = v;
    }
    for (int i = tid; i < 80 * 16; i += 320) {
        int r = i >> 4, c = (i & 15) << 2;
        int row = rb + r;
        float4 a = make_float4(0.f, 0.f, 0.f, 0.f);
        if (row < n) {
            const float4* p = (const float4*)(h1 + (size_t)row * 10 * 64 + c);
#pragma unroll
            for (int j = 0; j < 10; j++) {
                float4 t = p[j * 16];
                a.x += t.x; a.y += t.y; a.z += t.z; a.w += t.w;
            }
            a.x *= 0.1f; a.y *= 0.1f; a.z *= 0.1f; a.w *= 0.1f;
        }
        *(float4*)(Xs + r * 132 + 64 + c) = a;
    }
    for (int i = tid; i < 128 * 32; i += 320) {
        *(float4*)(Ws + i * 4) = *(const float4*)(w0 + i * 4);
    }
    __syncthreads();

    const int tx = tid & 15, ty = tid >> 4;
    unsigned long long acc2[4][4];
    gemm_core<128, 132>(Xs, Ws, tx, ty, acc2);

    float bv[8];
#pragma unroll
    for (int j = 0; j < 4; j++) { bv[j] = b0[tx * 4 + j]; bv[4 + j] = b0[64 + tx * 4 + j]; }

#pragma unroll
    for (int r = 0; r < 4; r++) {
        int row = rb + ty * 4 + r;
        if (row >= n) continue;
        float v[8];
        epi_relu(acc2[r], bv, v);
        float* dr = a01 + (size_t)row * 128;
        *(float4*)(dr + tx * 4)      = make_float4(v[0], v[1], v[2], v[3]);
        *(float4*)(dr + 64 + tx * 4) = make_float4(v[4], v[5], v[6], v[7]);
    }
}

// ---------------------------------------------------------------------------
// K2b: seg[g] += relu([a01 | ma12] @ w1 + b1). K=256, 80 rows/block,
// 320 threads, grid 125 (exactly one wave).
// smem: Xs 80x260 + Ws 256x128 = 214272 B -> 1 CTA/SM.
// ---------------------------------------------------------------------------
__global__ void __launch_bounds__(320)
k2b_fused(const float* __restrict__ a01, const float* __restrict__ ma12,
          const float* __restrict__ w1, const float* __restrict__ b1,
          const int* __restrict__ gid, float* __restrict__ seg, int n) {
    extern __shared__ float smem[];
    float* Xs = smem;               // 80 * 260
    float* Ws = smem + 80 * 260;    // 256 * 128

    const int tid = threadIdx.x;
    const int rb  = blockIdx.x * 80;

    for (int i = tid; i < 80 * 64; i += 320) {
        int r = i >> 6, c = (i & 63) << 2;
        int row = rb + r;
        float4 v = make_float4(0.f, 0.f, 0.f, 0.f);
        if (row < n) {
            if (c < 128) v = *(const float4*)(a01  + (size_t)row * 128 + c);
            else         v = *(const float4*)(ma12 + (size_t)row * 128 + c - 128);
        }
        *(float4*)(Xs + r * 260 + c) = v;
    }
    for (int i = tid; i < 256 * 32; i += 320) {
        *(float4*)(Ws + i * 4) = *(const float4*)(w1 + i * 4);
    }
    __syncthreads();

    const int tx = tid & 15, ty = tid >> 4;
    unsigned long long acc2[4][4];
    gemm_core<256, 260>(Xs, Ws, tx, ty, acc2);

    float bv[8];
#pragma unroll
    for (int j = 0; j < 4; j++) { bv[j] = b1[tx * 4 + j]; bv[4 + j] = b1[64 + tx * 4 + j]; }

#pragma unroll
    for (int r = 0; r < 4; r++) {
        int row = rb + ty * 4 + r;
        if (row >= n) continue;
        float v[8];
        epi_relu(acc2[r], bv, v);
        int g = gid[row];
        float* sp = seg + (size_t)g * 128;
#pragma unroll
        for (int j = 0; j < 4; j++) atomicAdd(sp + tx * 4 + j, v[j]);
#pragma unroll
        for (int j = 0; j < 4; j++) atomicAdd(sp + 64 + tx * 4 + j, v[4 + j]);
    }
}

// ---------------------------------------------------------------------------
// Readout MLP: one thread per graph.
// ---------------------------------------------------------------------------
__global__ void readout_kernel(const float* __restrict__ seg,
                               const float* __restrict__ wr1, const float* __restrict__ br1,
                               const float* __restrict__ wr2, const float* __restrict__ br2,
                               const float* __restrict__ wr3, const float* __restrict__ br3,
                               float* __restrict__ outp) {
    __shared__ float w1s[128 * 35];
    __shared__ float w2s[35 * 35];
    __shared__ float w3s[35], b1s[35], b2s[35];
    __shared__ float b3s;

    int tid = threadIdx.x;
    for (int i = tid; i < 128 * 35; i += blockDim.x) w1s[i] = wr1[i];
    for (int i = tid; i < 35 * 35;  i += blockDim.x) w2s[i] = wr2[i];
    if (tid < 35) { w3s[tid] = wr3[tid]; b1s[tid] = br1[tid]; b2s[tid] = br2[tid]; }
    if (tid == 0) b3s = br3[0];
    __syncthreads();

    if (tid >= G) return;

    const float SC = 1.0507009873554805f;
    const float AL = 1.6732632423543772f;

    const float* s = seg + tid * 128;
    float r1[35];
#pragma unroll
    for (int j = 0; j < 35; j++) r1[j] = b1s[j];
    for (int k = 0; k < 128; k++) {
        float x = s[k];
#pragma unroll
        for (int j = 0; j < 35; j++) r1[j] = fmaf(x, w1s[k * 35 + j], r1[j]);
    }
#pragma unroll
    for (int j = 0; j < 35; j++) {
        float x = r1[j];
        r1[j] = SC * (x > 0.0f ? x : AL * (expf(x) - 1.0f));
    }

    float r2[35];
#pragma unroll
    for (int j = 0; j < 35; j++) r2[j] = b2s[j];
#pragma unroll
    for (int k = 0; k < 35; k++) {
        float x = r1[k];
#pragma unroll
        for (int j = 0; j < 35; j++) r2[j] = fmaf(x, w2s[k * 35 + j], r2[j]);
    }
#pragma unroll
    for (int j = 0; j < 35; j++) {
        float x = r2[j];
        r2[j] = SC * (x > 0.0f ? x : AL * (expf(x) - 1.0f));
    }

    float r3 = b3s;
#pragma unroll
    for (int j = 0; j < 35; j++) r3 = fmaf(r2[j], w3s[j], r3);
    outp[tid] = r3;
}

// ---------------------------------------------------------------------------
extern "C" void kernel_launch(void* const* d_in, const int* in_sizes, int n_in,
                              void* d_out, int out_size) {
    const float* h0  = (const float*)d_in[0];
    const float* h1  = (const float*)d_in[1];
    const float* h2  = (const float*)d_in[2];
    const float* w0  = (const float*)d_in[3];
    const float* b0  = (const float*)d_in[4];
    const float* w1  = (const float*)d_in[5];
    const float* b1  = (const float*)d_in[6];
    const float* wr1 = (const float*)d_in[7];
    const float* br1 = (const float*)d_in[8];
    const float* wr2 = (const float*)d_in[9];
    const float* br2 = (const float*)d_in[10];
    const float* wr3 = (const float*)d_in[11];
    const float* br3 = (const float*)d_in[12];
    const int*   gid = (const int*)d_in[13];

    const int n  = in_sizes[0] / DIM;   // 10000
    const int r1 = in_sizes[1] / DIM;   // 100000

    float *ma12, *a01, *seg;
    cudaGetSymbolAddress((void**)&ma12, g_ma12);
    cudaGetSymbolAddress((void**)&a01,  g_a01);
    cudaGetSymbolAddress((void**)&seg,  g_seg);

    constexpr int SMEM_K1  = (80 * 132 + 128 * 128) * 4;   // 107776
    constexpr int SMEM_K2A = (80 * 132 + 128 * 128) * 4;   // 107776
    constexpr int SMEM_K2B = (80 * 260 + 256 * 128) * 4;   // 214272
    cudaFuncSetAttribute((const void*)k1_fused,
                         cudaFuncAttributeMaxDynamicSharedMemorySize, SMEM_K1);
    cudaFuncSetAttribute((const void*)k2a_fused,
                         cudaFuncAttributeMaxDynamicSharedMemorySize, SMEM_K2A);
    cudaFuncSetAttribute((const void*)k2b_fused,
                         cudaFuncAttributeMaxDynamicSharedMemorySize, SMEM_K2B);

    zero_seg_kernel<<<32, 256>>>();

    k1_fused<<<r1 / 80, 320, SMEM_K1>>>(h1, h2, w0, b0, ma12);

    k2a_fused<<<(n + 79) / 80, 320, SMEM_K2A>>>(h0, h1, w0, b0, a01, n);

    k2b_fused<<<(n + 79) / 80, 320, SMEM_K2B>>>(a01, ma12, w1, b1, gid, seg, n);

    readout_kernel<<<1, 128>>>(seg, wr1, br1, wr2, br2, wr3, br3, (float*)d_out);
}

// round 4
// speedup vs baseline: 1.5696x; 1.0386x over previous
#include <cuda_runtime.h>
#include <cstdint>
#include <cstddef>

// ---------------------------------------------------------------------------
// 2-layer GraphSAGE mean-aggregator + segment sum + SELU readout.
//
// R4:
//  K1 : ma12 = groupmean10( relu([h1 | groupmean25(h2)] @ w0 + b0) )
//       h2-mean LDGs interleaved with the K-half-1 FMAs (h1 columns) in one
//       unrolled region -> DRAM stays busy during compute. K-half-2 runs
//       after the mean lands in smem. 80 rows/CTA, 320 thr, 2 CTAs/SM.
//  K2 : a01-tile GEMM (w0) fused with round-1 GEMM (w1) + segment atomics.
//       grid 148 (all SMs), 544 thr (17 warps), 2x8 thread tiles, explicit
//       W/X register prefetch.
//  K3 : readout MLP.
// ---------------------------------------------------------------------------

static constexpr int NN  = 10000;
static constexpr int DIM = 64;
static constexpr int G   = 64;

__device__ float g_ma12[NN * 128];
__device__ float g_seg [G * 128];

// ---------------------------------------------------------------------------
__device__ __forceinline__ void fma2(unsigned long long& a,
                                     unsigned long long x, unsigned long long w) {
    asm("fma.rn.f32x2 %0, %1, %2, %3;" : "=l"(a) : "l"(x), "l"(w), "l"(a));
}
__device__ __forceinline__ unsigned long long pack2(float x) {
    unsigned long long r;
    asm("mov.b64 %0, {%1, %1};" : "=l"(r) : "f"(x));
    return r;
}
__device__ __forceinline__ void unpack2(unsigned long long v, float& lo, float& hi) {
    asm("mov.b64 {%0, %1}, %2;" : "=f"(lo), "=f"(hi) : "l"(v));
}

// One k-group (4 k) of the 4-row x 8-col GEMM. No internal prefetch
// (used inside the k1 fused region where h2 LDGs cover latency).
template <int KP>
__device__ __forceinline__ void kgroup4(const float* __restrict__ Xp,
                                        const float* __restrict__ WA,
                                        const float* __restrict__ WB,
                                        int g, unsigned long long (&acc2)[4][4]) {
    float4 x4[4];
#pragma unroll
    for (int r = 0; r < 4; r++) x4[r] = *(const float4*)(Xp + r * KP + g * 4);
#pragma unroll
    for (int kk = 0; kk < 4; kk++) {
        ulonglong2 wa = *(const ulonglong2*)(WA + (g * 4 + kk) * 128);
        ulonglong2 wb = *(const ulonglong2*)(WB + (g * 4 + kk) * 128);
#pragma unroll
        for (int r = 0; r < 4; r++) {
            float xs = kk == 0 ? x4[r].x : kk == 1 ? x4[r].y
                     : kk == 2 ? x4[r].z : x4[r].w;
            unsigned long long xx = pack2(xs);
            fma2(acc2[r][0], xx, wa.x);
            fma2(acc2[r][1], xx, wa.y);
            fma2(acc2[r][2], xx, wb.x);
            fma2(acc2[r][3], xx, wb.y);
        }
    }
}

// R-row x 8-col GEMM with explicit register prefetch of next-k W and
// next-group X (LDS issued ~16 FFMA2 ahead of use). Accumulates into acc2.
template <int K, int KP, int R, int UNR>
__device__ __forceinline__ void gemm_core_pf(const float* __restrict__ Xs,
                                             const float* __restrict__ Ws,
                                             int tx, int ty,
                                             unsigned long long (&acc2)[R][4]) {
    const float* Xp = Xs + ty * R * KP;
    const float* WA = Ws + tx * 4;
    const float* WB = Ws + 64 + tx * 4;
    constexpr int NG = K / 4;

    float4 xc[R];
#pragma unroll
    for (int r = 0; r < R; r++) xc[r] = *(const float4*)(Xp + r * KP);
    ulonglong2 wa = *(const ulonglong2*)(WA);
    ulonglong2 wb = *(const ulonglong2*)(WB);

#pragma unroll UNR
    for (int g = 0; g < NG; g++) {
        int gn = (g + 1 < NG) ? g + 1 : g;
        float4 xn[R];
#pragma unroll
        for (int r = 0; r < R; r++)
            xn[r] = *(const float4*)(Xp + r * KP + gn * 4);
#pragma unroll
        for (int kk = 0; kk < 4; kk++) {
            int k  = g * 4 + kk;
            int kn = (k + 1 < K) ? k + 1 : k;
            ulonglong2 wan = *(const ulonglong2*)(WA + kn * 128);
            ulonglong2 wbn = *(const ulonglong2*)(WB + kn * 128);
#pragma unroll
            for (int r = 0; r < R; r++) {
                float xs = kk == 0 ? xc[r].x : kk == 1 ? xc[r].y
                         : kk == 2 ? xc[r].z : xc[r].w;
                unsigned long long xx = pack2(xs);
                fma2(acc2[r][0], xx, wa.x);
                fma2(acc2[r][1], xx, wa.y);
                fma2(acc2[r][2], xx, wb.x);
                fma2(acc2[r][3], xx, wb.y);
            }
            wa = wan; wb = wbn;
        }
#pragma unroll
        for (int r = 0; r < R; r++) xc[r] = xn[r];
    }
}

// ---------------------------------------------------------------------------
// K1: 80 rows/block, 320 threads, grid 1250 (exact), 2 CTAs/SM.
// smem: Xs 80x132 + Ws 128x128 = 107776 B.
// ---------------------------------------------------------------------------
__global__ void __launch_bounds__(320, 2)
k1_fused(const float* __restrict__ h1, const float* __restrict__ h2,
         const float* __restrict__ w0, const float* __restrict__ b0,
         float* __restrict__ ma12) {
    extern __shared__ float smem[];
    float* Xs = smem;               // 80 * 132
    float* Ws = smem + 80 * 132;    // 128 * 128

    const int tid = threadIdx.x;
    const int rb  = blockIdx.x * 80;

    if (blockIdx.x == 0) {
        for (int i = tid; i < G * 128; i += 320) g_seg[i] = 0.0f;
    }

    // h1 tile -> Xs[:, 0:64]
    for (int i = tid; i < 80 * 16; i += 320) {
        int r = i >> 4, c = (i & 15) << 2;
        *(float4*)(Xs + r * 132 + c) =
            *(const float4*)(h1 + (size_t)(rb + r) * 64 + c);
    }
    // w0 -> Ws
    for (int i = tid; i < 128 * 32; i += 320) {
        *(float4*)(Ws + i * 4) = *(const float4*)(w0 + i * 4);
    }

    // h2 mean slots: 4 per thread
    const float* hp[4];
#pragma unroll
    for (int s = 0; s < 4; s++) {
        int idx = tid + s * 320;
        int r = idx >> 4, c = (idx & 15) << 2;
        hp[s] = h2 + (size_t)(rb + r) * 1600 + c;
    }
    float4 macc[4];
#pragma unroll
    for (int s = 0; s < 4; s++) macc[s] = make_float4(0.f, 0.f, 0.f, 0.f);

    // loop A: first 9 of 25 mean iterations (pure LDG; gets DRAM going)
#pragma unroll
    for (int j = 0; j < 9; j++) {
#pragma unroll
        for (int s = 0; s < 4; s++) {
            float4 t = *(const float4*)(hp[s] + j * 64);
            macc[s].x += t.x; macc[s].y += t.y;
            macc[s].z += t.z; macc[s].w += t.w;
        }
    }
    __syncthreads();

    const int tx = tid & 15, ty = tid >> 4;
    const float* Xp = Xs + ty * 4 * 132;
    const float* WA = Ws + tx * 4;
    const float* WB = Ws + 64 + tx * 4;

    unsigned long long acc2[4][4];
#pragma unroll
    for (int r = 0; r < 4; r++)
#pragma unroll
        for (int p = 0; p < 4; p++) acc2[r][p] = 0ULL;

    // loop B: 16 mean iterations interleaved 1:1 with 16 k-groups (k=0..63,
    // h1 columns only) — LDGs and FMAs share one unrolled region.
#pragma unroll 4
    for (int j = 0; j < 16; j++) {
#pragma unroll
        for (int s = 0; s < 4; s++) {
            float4 t = *(const float4*)(hp[s] + (9 + j) * 64);
            macc[s].x += t.x; macc[s].y += t.y;
            macc[s].z += t.z; macc[s].w += t.w;
        }
        kgroup4<132>(Xp, WA, WB, j, acc2);
    }

    // mean25 -> Xs[:, 64:128]  (disjoint from cols 0:64 still being read)
#pragma unroll
    for (int s = 0; s < 4; s++) {
        int idx = tid + s * 320;
        int r = idx >> 4, c = (idx & 15) << 2;
        *(float4*)(Xs + r * 132 + 64 + c) =
            make_float4(macc[s].x * 0.04f, macc[s].y * 0.04f,
                        macc[s].z * 0.04f, macc[s].w * 0.04f);
    }
    __syncthreads();

    // K-half-2: k=64..127 over the mean columns
    gemm_core_pf<64, 132, 4, 4>(Xs + 64, Ws + 64 * 128, tx, ty, acc2);

    float bv[8];
#pragma unroll
    for (int j = 0; j < 4; j++) {
        bv[j]     = b0[tx * 4 + j];
        bv[4 + j] = b0[64 + tx * 4 + j];
    }

    __syncthreads();   // all Xs reads done; reuse for relu tile
#pragma unroll
    for (int r = 0; r < 4; r++) {
        float v[8];
#pragma unroll
        for (int p = 0; p < 4; p++) unpack2(acc2[r][p], v[2 * p], v[2 * p + 1]);
#pragma unroll
        for (int j = 0; j < 8; j++) {
            float t = v[j] + bv[j];
            v[j] = t > 0.0f ? t : 0.0f;
        }
        float* dr = Xs + (ty * 4 + r) * 132;
        *(float4*)(dr + tx * 4)      = make_float4(v[0], v[1], v[2], v[3]);
        *(float4*)(dr + 64 + tx * 4) = make_float4(v[4], v[5], v[6], v[7]);
    }
    __syncthreads();

    // group mean of 10 -> ma12 (8 groups x 128 cols per block)
    for (int o = tid; o < 1024; o += 320) {
        int gl = o >> 7, c = o & 127;
        float s = 0.0f;
#pragma unroll
        for (int r2 = 0; r2 < 10; r2++) s += Xs[(gl * 10 + r2) * 132 + c];
        ma12[(size_t)(blockIdx.x * 8 + gl) * 128 + c] = s * 0.1f;
    }
}

// ---------------------------------------------------------------------------
// K2: fused a01-GEMM (w0) + round-1 GEMM (w1) + segment atomics.
// grid 148, 544 threads (tx16 x ty34, 2 rows/thread), 68 rows/CTA.
// smem: X2 68x260 (70720 B) + Ws 256x128 (131072 B) = 201792 B.
// X1 = [h0 | mean10(h1)] lives in X2[:,128:256]; GEMM1 writes a01 into
// X2[:,0:128] (disjoint cols, no race); then ma12 overwrites X2[:,128:256].
// ---------------------------------------------------------------------------
__global__ void __launch_bounds__(544, 1)
k2_fused(const float* __restrict__ h0, const float* __restrict__ h1,
         const float* __restrict__ ma12,
         const float* __restrict__ w0, const float* __restrict__ b0,
         const float* __restrict__ w1, const float* __restrict__ b1,
         const int* __restrict__ gid, float* __restrict__ seg, int n) {
    extern __shared__ float smem[];
    float* X2 = smem;               // 68 * 260
    float* Ws = smem + 68 * 260;    // up to 256 * 128

    const int tid = threadIdx.x;
    const int rb  = blockIdx.x * 68;

    // X1: h0 -> X2[:,128:192]
    for (int i = tid; i < 68 * 16; i += 544) {
        int r = i >> 4, c = (i & 15) << 2;
        int row = rb + r;
        float4 v = make_float4(0.f, 0.f, 0.f, 0.f);
        if (row < n) v = *(const float4*)(h0 + (size_t)row * 64 + c);
        *(float4*)(X2 + r * 260 + 128 + c) = v;
    }
    // X1: mean10(h1) -> X2[:,192:256]
    for (int i = tid; i < 68 * 16; i += 544) {
        int r = i >> 4, c = (i & 15) << 2;
        int row = rb + r;
        float4 a = make_float4(0.f, 0.f, 0.f, 0.f);
        if (row < n) {
            const float4* p = (const float4*)(h1 + (size_t)row * 640 + c);
#pragma unroll
            for (int j = 0; j < 10; j++) {
                float4 t = p[j * 16];
                a.x += t.x; a.y += t.y; a.z += t.z; a.w += t.w;
            }
            a.x *= 0.1f; a.y *= 0.1f; a.z *= 0.1f; a.w *= 0.1f;
        }
        *(float4*)(X2 + r * 260 + 192 + c) = a;
    }
    // w0 -> Ws (64 KB)
    for (int i = tid; i < 128 * 32; i += 544) {
        *(float4*)(Ws + i * 4) = *(const float4*)(w0 + i * 4);
    }
    __syncthreads();

    const int tx = tid & 15, ty = tid >> 4;   // ty 0..33

    // GEMM1: a01 tile = relu(X1 @ w0 + b0)
    unsigned long long acc1[2][4];
#pragma unroll
    for (int r = 0; r < 2; r++)
#pragma unroll
        for (int p = 0; p < 4; p++) acc1[r][p] = 0ULL;
    gemm_core_pf<128, 260, 2, 4>(X2 + 128, Ws, tx, ty, acc1);

    float bv0[8];
#pragma unroll
    for (int j = 0; j < 4; j++) {
        bv0[j]     = b0[tx * 4 + j];
        bv0[4 + j] = b0[64 + tx * 4 + j];
    }
#pragma unroll
    for (int r = 0; r < 2; r++) {
        float v[8];
#pragma unroll
        for (int p = 0; p < 4; p++) unpack2(acc1[r][p], v[2 * p], v[2 * p + 1]);
#pragma unroll
        for (int j = 0; j < 8; j++) {
            float t = v[j] + bv0[j];
            v[j] = t > 0.0f ? t : 0.0f;
        }
        float* dr = X2 + (ty * 2 + r) * 260;
        *(float4*)(dr + tx * 4)      = make_float4(v[0], v[1], v[2], v[3]);
        *(float4*)(dr + 64 + tx * 4) = make_float4(v[4], v[5], v[6], v[7]);
    }
    __syncthreads();

    // ma12 -> X2[:,128:256]
    for (int i = tid; i < 68 * 32; i += 544) {
        int r = i >> 5, c = (i & 31) << 2;
        int row = rb + r;
        float4 v = make_float4(0.f, 0.f, 0.f, 0.f);
        if (row < n) v = *(const float4*)(ma12 + (size_t)row * 128 + c);
        *(float4*)(X2 + r * 260 + 128 + c) = v;
    }
    // w1 -> Ws (128 KB)
    for (int i = tid; i < 256 * 32; i += 544) {
        *(float4*)(Ws + i * 4) = *(const float4*)(w1 + i * 4);
    }
    __syncthreads();

    // GEMM2: out = relu([a01 | ma12] @ w1 + b1) -> segment atomics
    unsigned long long acc2[2][4];
#pragma unroll
    for (int r = 0; r < 2; r++)
#pragma unroll
        for (int p = 0; p < 4; p++) acc2[r][p] = 0ULL;
    gemm_core_pf<256, 260, 2, 2>(X2, Ws, tx, ty, acc2);

    float bv1[8];
#pragma unroll
    for (int j = 0; j < 4; j++) {
        bv1[j]     = b1[tx * 4 + j];
        bv1[4 + j] = b1[64 + tx * 4 + j];
    }
#pragma unroll
    for (int r = 0; r < 2; r++) {
        int row = rb + ty * 2 + r;
        if (row >= n) continue;
        float v[8];
#pragma unroll
        for (int p = 0; p < 4; p++) unpack2(acc2[r][p], v[2 * p], v[2 * p + 1]);
        int g = gid[row];
        float* sp = seg + (size_t)g * 128;
#pragma unroll
        for (int j = 0; j < 4; j++) {
            float t = v[j] + bv1[j];
            atomicAdd(sp + tx * 4 + j, t > 0.0f ? t : 0.0f);
        }
#pragma unroll
        for (int j = 0; j < 4; j++) {
            float t = v[4 + j] + bv1[4 + j];
            atomicAdd(sp + 64 + tx * 4 + j, t > 0.0f ? t : 0.0f);
        }
    }
}

// ---------------------------------------------------------------------------
// Readout MLP: one thread per graph.
// ---------------------------------------------------------------------------
__global__ void readout_kernel(const float* __restrict__ seg,
                               const float* __restrict__ wr1, const float* __restrict__ br1,
                               const float* __restrict__ wr2, const float* __restrict__ br2,
                               const float* __restrict__ wr3, const float* __restrict__ br3,
                               float* __restrict__ outp) {
    __shared__ float w1s[128 * 35];
    __shared__ float w2s[35 * 35];
    __shared__ float w3s[35], b1s[35], b2s[35];
    __shared__ float b3s;

    int tid = threadIdx.x;
    for (int i = tid; i < 128 * 35; i += blockDim.x) w1s[i] = wr1[i];
    for (int i = tid; i < 35 * 35;  i += blockDim.x) w2s[i] = wr2[i];
    if (tid < 35) { w3s[tid] = wr3[tid]; b1s[tid] = br1[tid]; b2s[tid] = br2[tid]; }
    if (tid == 0) b3s = br3[0];
    __syncthreads();

    if (tid >= G) return;

    const float SC = 1.0507009873554805f;
    const float AL = 1.6732632423543772f;

    const float* s = seg + tid * 128;
    float r1[35];
#pragma unroll
    for (int j = 0; j < 35; j++) r1[j] = b1s[j];
    for (int k = 0; k < 128; k++) {
        float x = s[k];
#pragma unroll
        for (int j = 0; j < 35; j++) r1[j] = fmaf(x, w1s[k * 35 + j], r1[j]);
    }
#pragma unroll
    for (int j = 0; j < 35; j++) {
        float x = r1[j];
        r1[j] = SC * (x > 0.0f ? x : AL * (expf(x) - 1.0f));
    }

    float r2[35];
#pragma unroll
    for (int j = 0; j < 35; j++) r2[j] = b2s[j];
#pragma unroll
    for (int k = 0; k < 35; k++) {
        float x = r1[k];
#pragma unroll
        for (int j = 0; j < 35; j++) r2[j] = fmaf(x, w2s[k * 35 + j], r2[j]);
    }
#pragma unroll
    for (int j = 0; j < 35; j++) {
        float x = r2[j];
        r2[j] = SC * (x > 0.0f ? x : AL * (expf(x) - 1.0f));
    }

    float r3 = b3s;
#pragma unroll
    for (int j = 0; j < 35; j++) r3 = fmaf(r2[j], w3s[j], r3);
    outp[tid] = r3;
}

// ---------------------------------------------------------------------------
extern "C" void kernel_launch(void* const* d_in, const int* in_sizes, int n_in,
                              void* d_out, int out_size) {
    const float* h0  = (const float*)d_in[0];
    const float* h1  = (const float*)d_in[1];
    const float* h2  = (const float*)d_in[2];
    const float* w0  = (const float*)d_in[3];
    const float* b0  = (const float*)d_in[4];
    const float* w1  = (const float*)d_in[5];
    const float* b1  = (const float*)d_in[6];
    const float* wr1 = (const float*)d_in[7];
    const float* br1 = (const float*)d_in[8];
    const float* wr2 = (const float*)d_in[9];
    const float* br2 = (const float*)d_in[10];
    const float* wr3 = (const float*)d_in[11];
    const float* br3 = (const float*)d_in[12];
    const int*   gid = (const int*)d_in[13];

    const int n  = in_sizes[0] / DIM;   // 10000
    const int r1 = in_sizes[1] / DIM;   // 100000

    float *ma12, *seg;
    cudaGetSymbolAddress((void**)&ma12, g_ma12);
    cudaGetSymbolAddress((void**)&seg,  g_seg);

    constexpr int SMEM_K1 = (80 * 132 + 128 * 128) * 4;   // 107776
    constexpr int SMEM_K2 = (68 * 260 + 256 * 128) * 4;   // 201792
    cudaFuncSetAttribute((const void*)k1_fused,
                         cudaFuncAttributeMaxDynamicSharedMemorySize, SMEM_K1);
    cudaFuncSetAttribute((const void*)k2_fused,
                         cudaFuncAttributeMaxDynamicSharedMemorySize, SMEM_K2);

    // K1: streams 640 MB of h2 with GEMM hidden underneath; zeroes seg.
    k1_fused<<<r1 / 80, 320, SMEM_K1>>>(h1, h2, w0, b0, ma12);

    // K2: a01 + round-1 GEMM + fused segment-sum (grid = 148, one wave)
    k2_fused<<<148, 544, SMEM_K2>>>(h0, h1, ma12, w0, b0, w1, b1, gid, seg, n);

    // K3: readout
    readout_kernel<<<1, 128>>>(seg, wr1, br1, wr2, br2, wr3, br3, (float*)d_out);
}

// round 5
// speedup vs baseline: 1.7462x; 1.1125x over previous
#include <cuda_runtime.h>
#include <cstdint>
#include <cstddef>

// ---------------------------------------------------------------------------
// 2-layer GraphSAGE mean-aggregator + segment sum + SELU readout.
//
// R5:
//  K1 : persistent (grid 148), double-buffered tiles. Tile t's full 128-k
//       GEMM interleaves with tile (t+1)'s h2-mean LDGs + h1 loads, so the
//       640MB h2 stream never pauses. 80 rows/tile, 320 thr, 1 CTA/SM.
//  K2a: a01 = relu([h0 | mean10(h1)] @ w0 + b0). 640 thr, 80 rows.
//  K2b: seg += relu([a01 | ma12] @ w1 + b1). 640 thr, 80 rows, atomics.
//  K3 : readout MLP.
// ---------------------------------------------------------------------------

static constexpr int NN  = 10000;
static constexpr int DIM = 64;
static constexpr int G   = 64;

__device__ float g_ma12[NN * 128];
__device__ float g_a01 [NN * 128];
__device__ float g_seg [G * 128];

// ---------------------------------------------------------------------------
__device__ __forceinline__ void fma2(unsigned long long& a,
                                     unsigned long long x, unsigned long long w) {
    asm("fma.rn.f32x2 %0, %1, %2, %3;" : "=l"(a) : "l"(x), "l"(w), "l"(a));
}
__device__ __forceinline__ unsigned long long pack2(float x) {
    unsigned long long r;
    asm("mov.b64 %0, {%1, %1};" : "=l"(r) : "f"(x));
    return r;
}
__device__ __forceinline__ void unpack2(unsigned long long v, float& lo, float& hi) {
    asm("mov.b64 {%0, %1}, %2;" : "=f"(lo), "=f"(hi) : "l"(v));
}

// One k-group (4 k) of the 4-row x 8-col GEMM (cols tx*4.., 64+tx*4..).
template <int KP>
__device__ __forceinline__ void kgroup4(const float* __restrict__ Xp,
                                        const float* __restrict__ WA,
                                        const float* __restrict__ WB,
                                        int g, unsigned long long (&acc2)[4][4]) {
    float4 x4[4];
#pragma unroll
    for (int r = 0; r < 4; r++) x4[r] = *(const float4*)(Xp + r * KP + g * 4);
#pragma unroll
    for (int kk = 0; kk < 4; kk++) {
        ulonglong2 wa = *(const ulonglong2*)(WA + (g * 4 + kk) * 128);
        ulonglong2 wb = *(const ulonglong2*)(WB + (g * 4 + kk) * 128);
#pragma unroll
        for (int r = 0; r < 4; r++) {
            float xs = kk == 0 ? x4[r].x : kk == 1 ? x4[r].y
                     : kk == 2 ? x4[r].z : x4[r].w;
            unsigned long long xx = pack2(xs);
            fma2(acc2[r][0], xx, wa.x);
            fma2(acc2[r][1], xx, wa.y);
            fma2(acc2[r][2], xx, wb.x);
            fma2(acc2[r][3], xx, wb.y);
        }
    }
}

// Plain R-row x 8-col GEMM (R3-proven core, no prefetch tricks).
template <int K, int KP, int R>
__device__ __forceinline__ void gemm_core(const float* __restrict__ Xs,
                                          const float* __restrict__ Ws,
                                          int tx, int ty,
                                          unsigned long long (&acc2)[R][4]) {
    const float* Xp = Xs + ty * R * KP;
    const float* WA = Ws + tx * 4;
    const float* WB = Ws + 64 + tx * 4;
#pragma unroll 4
    for (int k = 0; k < K; k += 4) {
        float4 x4[R];
#pragma unroll
        for (int r = 0; r < R; r++) x4[r] = *(const float4*)(Xp + r * KP + k);
#pragma unroll
        for (int kk = 0; kk < 4; kk++) {
            ulonglong2 wa = *(const ulonglong2*)(WA + (k + kk) * 128);
            ulonglong2 wb = *(const ulonglong2*)(WB + (k + kk) * 128);
#pragma unroll
            for (int r = 0; r < R; r++) {
                float xs = kk == 0 ? x4[r].x : kk == 1 ? x4[r].y
                         : kk == 2 ? x4[r].z : x4[r].w;
                unsigned long long xx = pack2(xs);
                fma2(acc2[r][0], xx, wa.x);
                fma2(acc2[r][1], xx, wa.y);
                fma2(acc2[r][2], xx, wb.x);
                fma2(acc2[r][3], xx, wb.y);
            }
        }
    }
}

// ---------------------------------------------------------------------------
// K1: persistent, double-buffered. grid 148, 320 threads, 1 CTA/SM.
// smem: Xs[2] 80x132 (84480 B) + Ws 128x128 (65536 B) = 150016 B.
// ---------------------------------------------------------------------------
__global__ void __launch_bounds__(320, 1)
k1_persist(const float* __restrict__ h1, const float* __restrict__ h2,
           const float* __restrict__ w0, const float* __restrict__ b0,
           float* __restrict__ ma12, int ntiles) {
    extern __shared__ float smem[];
    float* Ws = smem + 2 * 80 * 132;    // 128 * 128

    const int tid = threadIdx.x;
    const int tx  = tid & 15, ty = tid >> 4;

    if (blockIdx.x == 0) {
        for (int i = tid; i < G * 128; i += 320) g_seg[i] = 0.0f;
    }

    // w0 -> Ws (once)
    for (int i = tid; i < 128 * 32; i += 320) {
        *(float4*)(Ws + i * 4) = *(const float4*)(w0 + i * 4);
    }

    // per-thread tile slots (4): slot s covers row r_s, cols c_s..c_s+3
    int r_s[4], c_s[4];
#pragma unroll
    for (int s = 0; s < 4; s++) {
        int idx = tid + s * 320;
        r_s[s] = idx >> 4;
        c_s[s] = (idx & 15) << 2;
    }

    float bv[8];
#pragma unroll
    for (int j = 0; j < 4; j++) {
        bv[j]     = b0[tx * 4 + j];
        bv[4 + j] = b0[64 + tx * 4 + j];
    }

    int t = blockIdx.x;
    if (t >= ntiles) return;

    // ---- build first tile into buffer 0 ----
    {
        int rb = t * 80;
        float* X0 = smem;
#pragma unroll
        for (int s = 0; s < 4; s++) {
            *(float4*)(X0 + r_s[s] * 132 + c_s[s]) =
                *(const float4*)(h1 + (size_t)(rb + r_s[s]) * 64 + c_s[s]);
        }
        float4 m2[4];
#pragma unroll
        for (int s = 0; s < 4; s++) m2[s] = make_float4(0.f, 0.f, 0.f, 0.f);
#pragma unroll 5
        for (int j = 0; j < 25; j++) {
#pragma unroll
            for (int s = 0; s < 4; s++) {
                float4 u = *(const float4*)(h2 + (size_t)(rb + r_s[s]) * 1600
                                            + c_s[s] + j * 64);
                m2[s].x += u.x; m2[s].y += u.y; m2[s].z += u.z; m2[s].w += u.w;
            }
        }
#pragma unroll
        for (int s = 0; s < 4; s++) {
            *(float4*)(X0 + r_s[s] * 132 + 64 + c_s[s]) =
                make_float4(m2[s].x * 0.04f, m2[s].y * 0.04f,
                            m2[s].z * 0.04f, m2[s].w * 0.04f);
        }
    }
    __syncthreads();

    int cur = 0;
    while (t < ntiles) {
        const int tn = t + gridDim.x;
        float* Xc = smem + cur * (80 * 132);
        float* Xn = smem + (cur ^ 1) * (80 * 132);
        const float* Xp = Xc + ty * 4 * 132;
        const float* WA = Ws + tx * 4;
        const float* WB = Ws + 64 + tx * 4;

        unsigned long long acc2[4][4];
#pragma unroll
        for (int r = 0; r < 4; r++)
#pragma unroll
            for (int p = 0; p < 4; p++) acc2[r][p] = 0ULL;

        if (tn < ntiles) {
            // ---- GEMM(cur) interleaved with next-tile h2 mean + h1 loads ----
            const int rbn = tn * 80;
            const float* h2n = h2 + (size_t)rbn * 1600;
            float4 m2[4];
#pragma unroll
            for (int s = 0; s < 4; s++) m2[s] = make_float4(0.f, 0.f, 0.f, 0.f);

#pragma unroll 5
            for (int g = 0; g < 25; g++) {
#pragma unroll
                for (int s = 0; s < 4; s++) {
                    float4 u = *(const float4*)(h2n + (size_t)r_s[s] * 1600
                                                + c_s[s] + g * 64);
                    m2[s].x += u.x; m2[s].y += u.y; m2[s].z += u.z; m2[s].w += u.w;
                }
                kgroup4<132>(Xp, WA, WB, g, acc2);
            }
            // h1(next) -> Xn[:,0:64]
#pragma unroll
            for (int s = 0; s < 4; s++) {
                *(float4*)(Xn + r_s[s] * 132 + c_s[s]) =
                    *(const float4*)(h1 + (size_t)(rbn + r_s[s]) * 64 + c_s[s]);
            }
#pragma unroll
            for (int g = 25; g < 32; g++) kgroup4<132>(Xp, WA, WB, g, acc2);
            // mean25(next) -> Xn[:,64:128]
#pragma unroll
            for (int s = 0; s < 4; s++) {
                *(float4*)(Xn + r_s[s] * 132 + 64 + c_s[s]) =
                    make_float4(m2[s].x * 0.04f, m2[s].y * 0.04f,
                                m2[s].z * 0.04f, m2[s].w * 0.04f);
            }
        } else {
            // last tile: plain GEMM
#pragma unroll 4
            for (int g = 0; g < 32; g++) kgroup4<132>(Xp, WA, WB, g, acc2);
        }
        __syncthreads();   // GEMM reads of cur done; Xn stores complete

        // epilogue: bias + relu -> back into Xc
#pragma unroll
        for (int r = 0; r < 4; r++) {
            float v[8];
#pragma unroll
            for (int p = 0; p < 4; p++) unpack2(acc2[r][p], v[2 * p], v[2 * p + 1]);
#pragma unroll
            for (int j = 0; j < 8; j++) {
                float q = v[j] + bv[j];
                v[j] = q > 0.0f ? q : 0.0f;
            }
            float* dr = Xc + (ty * 4 + r) * 132;
            *(float4*)(dr + tx * 4)      = make_float4(v[0], v[1], v[2], v[3]);
            *(float4*)(dr + 64 + tx * 4) = make_float4(v[4], v[5], v[6], v[7]);
        }
        __syncthreads();

        // mean10 -> ma12 (8 groups x 128 cols)
        for (int o = tid; o < 1024; o += 320) {
            int gl = o >> 7, c = o & 127;
            float s = 0.0f;
#pragma unroll
            for (int r2 = 0; r2 < 10; r2++) s += Xc[(gl * 10 + r2) * 132 + c];
            ma12[(size_t)(t * 8 + gl) * 128 + c] = s * 0.1f;
        }
        __syncthreads();   // cur free for reuse

        t = tn;
        cur ^= 1;
    }
}

// ---------------------------------------------------------------------------
// K2a: a01 = relu([h0 | mean10(h1)] @ w0 + b0). 80 rows, 640 thr (R=2).
// smem: Xs 80x132 + Ws 128x128 = 107776 B.
// ---------------------------------------------------------------------------
__global__ void __launch_bounds__(640)
k2a_fused(const float* __restrict__ h0, const float* __restrict__ h1,
          const float* __restrict__ w0, const float* __restrict__ b0,
          float* __restrict__ a01, int n) {
    extern __shared__ float smem[];
    float* Xs = smem;               // 80 * 132
    float* Ws = smem + 80 * 132;    // 128 * 128

    const int tid = threadIdx.x;
    const int rb  = blockIdx.x * 80;

    for (int i = tid; i < 80 * 16; i += 640) {
        int r = i >> 4, c = (i & 15) << 2;
        int row = rb + r;
        float4 v = make_float4(0.f, 0.f, 0.f, 0.f);
        if (row < n) v = *(const float4*)(h0 + (size_t)row * 64 + c);
        *(float4*)(Xs + r * 132 + c) = v;
    }
    for (int i = tid; i < 80 * 16; i += 640) {
        int r = i >> 4, c = (i & 15) << 2;
        int row = rb + r;
        float4 a = make_float4(0.f, 0.f, 0.f, 0.f);
        if (row < n) {
            const float4* p = (const float4*)(h1 + (size_t)row * 640 + c);
#pragma unroll
            for (int j = 0; j < 10; j++) {
                float4 u = p[j * 16];
                a.x += u.x; a.y += u.y; a.z += u.z; a.w += u.w;
            }
            a.x *= 0.1f; a.y *= 0.1f; a.z *= 0.1f; a.w *= 0.1f;
        }
        *(float4*)(Xs + r * 132 + 64 + c) = a;
    }
    for (int i = tid; i < 128 * 32; i += 640) {
        *(float4*)(Ws + i * 4) = *(const float4*)(w0 + i * 4);
    }
    __syncthreads();

    const int tx = tid & 15, ty = tid >> 4;   // ty 0..39
    unsigned long long acc2[2][4];
#pragma unroll
    for (int r = 0; r < 2; r++)
#pragma unroll
        for (int p = 0; p < 4; p++) acc2[r][p] = 0ULL;
    gemm_core<128, 132, 2>(Xs, Ws, tx, ty, acc2);

    float bv[8];
#pragma unroll
    for (int j = 0; j < 4; j++) {
        bv[j]     = b0[tx * 4 + j];
        bv[4 + j] = b0[64 + tx * 4 + j];
    }
#pragma unroll
    for (int r = 0; r < 2; r++) {
        int row = rb + ty * 2 + r;
        if (row >= n) continue;
        float v[8];
#pragma unroll
        for (int p = 0; p < 4; p++) unpack2(acc2[r][p], v[2 * p], v[2 * p + 1]);
#pragma unroll
        for (int j = 0; j < 8; j++) {
            float q = v[j] + bv[j];
            v[j] = q > 0.0f ? q : 0.0f;
        }
        float* dr = a01 + (size_t)row * 128;
        *(float4*)(dr + tx * 4)      = make_float4(v[0], v[1], v[2], v[3]);
        *(float4*)(dr + 64 + tx * 4) = make_float4(v[4], v[5], v[6], v[7]);
    }
}

// ---------------------------------------------------------------------------
// K2b: seg[g] += relu([a01 | ma12] @ w1 + b1). K=256, 80 rows, 640 thr (R=2).
// smem: Xs 80x260 + Ws 256x128 = 214272 B. grid 125 (one wave).
// ---------------------------------------------------------------------------
__global__ void __launch_bounds__(640)
k2b_fused(const float* __restrict__ a01, const float* __restrict__ ma12,
          const float* __restrict__ w1, const float* __restrict__ b1,
          const int* __restrict__ gid, float* __restrict__ seg, int n) {
    extern __shared__ float smem[];
    float* Xs = smem;               // 80 * 260
    float* Ws = smem + 80 * 260;    // 256 * 128

    const int tid = threadIdx.x;
    const int rb  = blockIdx.x * 80;

    for (int i = tid; i < 80 * 64; i += 640) {
        int r = i >> 6, c = (i & 63) << 2;
        int row = rb + r;
        float4 v = make_float4(0.f, 0.f, 0.f, 0.f);
        if (row < n) {
            if (c < 128) v = *(const float4*)(a01  + (size_t)row * 128 + c);
            else         v = *(const float4*)(ma12 + (size_t)row * 128 + c - 128);
        }
        *(float4*)(Xs + r * 260 + c) = v;
    }
    for (int i = tid; i < 256 * 32; i += 640) {
        *(float4*)(Ws + i * 4) = *(const float4*)(w1 + i * 4);
    }
    __syncthreads();

    const int tx = tid & 15, ty = tid >> 4;   // ty 0..39
    unsigned long long acc2[2][4];
#pragma unroll
    for (int r = 0; r < 2; r++)
#pragma unroll
        for (int p = 0; p < 4; p++) acc2[r][p] = 0ULL;
    gemm_core<256, 260, 2>(Xs, Ws, tx, ty, acc2);

    float bv[8];
#pragma unroll
    for (int j = 0; j < 4; j++) {
        bv[j]     = b1[tx * 4 + j];
        bv[4 + j] = b1[64 + tx * 4 + j];
    }
#pragma unroll
    for (int r = 0; r < 2; r++) {
        int row = rb + ty * 2 + r;
        if (row >= n) continue;
        float v[8];
#pragma unroll
        for (int p = 0; p < 4; p++) unpack2(acc2[r][p], v[2 * p], v[2 * p + 1]);
        int g = gid[row];
        float* sp = seg + (size_t)g * 128;
#pragma unroll
        for (int j = 0; j < 4; j++) {
            float q = v[j] + bv[j];
            atomicAdd(sp + tx * 4 + j, q > 0.0f ? q : 0.0f);
        }
#pragma unroll
        for (int j = 0; j < 4; j++) {
            float q = v[4 + j] + bv[4 + j];
            atomicAdd(sp + 64 + tx * 4 + j, q > 0.0f ? q : 0.0f);
        }
    }
}

// ---------------------------------------------------------------------------
// Readout MLP: one thread per graph.
// ---------------------------------------------------------------------------
__global__ void readout_kernel(const float* __restrict__ seg,
                               const float* __restrict__ wr1, const float* __restrict__ br1,
                               const float* __restrict__ wr2, const float* __restrict__ br2,
                               const float* __restrict__ wr3, const float* __restrict__ br3,
                               float* __restrict__ outp) {
    __shared__ float w1s[128 * 35];
    __shared__ float w2s[35 * 35];
    __shared__ float w3s[35], b1s[35], b2s[35];
    __shared__ float b3s;

    int tid = threadIdx.x;
    for (int i = tid; i < 128 * 35; i += blockDim.x) w1s[i] = wr1[i];
    for (int i = tid; i < 35 * 35;  i += blockDim.x) w2s[i] = wr2[i];
    if (tid < 35) { w3s[tid] = wr3[tid]; b1s[tid] = br1[tid]; b2s[tid] = br2[tid]; }
    if (tid == 0) b3s = br3[0];
    __syncthreads();

    if (tid >= G) return;

    const float SC = 1.0507009873554805f;
    const float AL = 1.6732632423543772f;

    const float* s = seg + tid * 128;
    float r1[35];
#pragma unroll
    for (int j = 0; j < 35; j++) r1[j] = b1s[j];
    for (int k = 0; k < 128; k++) {
        float x = s[k];
#pragma unroll
        for (int j = 0; j < 35; j++) r1[j] = fmaf(x, w1s[k * 35 + j], r1[j]);
    }
#pragma unroll
    for (int j = 0; j < 35; j++) {
        float x = r1[j];
        r1[j] = SC * (x > 0.0f ? x : AL * (expf(x) - 1.0f));
    }

    float r2[35];
#pragma unroll
    for (int j = 0; j < 35; j++) r2[j] = b2s[j];
#pragma unroll
    for (int k = 0; k < 35; k++) {
        float x = r1[k];
#pragma unroll
        for (int j = 0; j < 35; j++) r2[j] = fmaf(x, w2s[k * 35 + j], r2[j]);
    }
#pragma unroll
    for (int j = 0; j < 35; j++) {
        float x = r2[j];
        r2[j] = SC * (x > 0.0f ? x : AL * (expf(x) - 1.0f));
    }

    float r3 = b3s;
#pragma unroll
    for (int j = 0; j < 35; j++) r3 = fmaf(r2[j], w3s[j], r3);
    outp[tid] = r3;
}

// ---------------------------------------------------------------------------
extern "C" void kernel_launch(void* const* d_in, const int* in_sizes, int n_in,
                              void* d_out, int out_size) {
    const float* h0  = (const float*)d_in[0];
    const float* h1  = (const float*)d_in[1];
    const float* h2  = (const float*)d_in[2];
    const float* w0  = (const float*)d_in[3];
    const float* b0  = (const float*)d_in[4];
    const float* w1  = (const float*)d_in[5];
    const float* b1  = (const float*)d_in[6];
    const float* wr1 = (const float*)d_in[7];
    const float* br1 = (const float*)d_in[8];
    const float* wr2 = (const float*)d_in[9];
    const float* br2 = (const float*)d_in[10];
    const float* wr3 = (const float*)d_in[11];
    const float* br3 = (const float*)d_in[12];
    const int*   gid = (const int*)d_in[13];

    const int n  = in_sizes[0] / DIM;   // 10000
    const int r1 = in_sizes[1] / DIM;   // 100000
    const int ntiles = r1 / 80;         // 1250

    float *ma12, *a01, *seg;
    cudaGetSymbolAddress((void**)&ma12, g_ma12);
    cudaGetSymbolAddress((void**)&a01,  g_a01);
    cudaGetSymbolAddress((void**)&seg,  g_seg);

    constexpr int SMEM_K1  = (2 * 80 * 132 + 128 * 128) * 4;  // 150016
    constexpr int SMEM_K2A = (80 * 132 + 128 * 128) * 4;      // 107776
    constexpr int SMEM_K2B = (80 * 260 + 256 * 128) * 4;      // 214272
    cudaFuncSetAttribute((const void*)k1_persist,
                         cudaFuncAttributeMaxDynamicSharedMemorySize, SMEM_K1);
    cudaFuncSetAttribute((const void*)k2a_fused,
                         cudaFuncAttributeMaxDynamicSharedMemorySize, SMEM_K2A);
    cudaFuncSetAttribute((const void*)k2b_fused,
                         cudaFuncAttributeMaxDynamicSharedMemorySize, SMEM_K2B);

    // K1: persistent h2 stream + GEMM + mean10; also zeroes seg.
    k1_persist<<<148, 320, SMEM_K1>>>(h1, h2, w0, b0, ma12, ntiles);

    // K2a / K2b
    k2a_fused<<<(n + 79) / 80, 640, SMEM_K2A>>>(h0, h1, w0, b0, a01, n);
    k2b_fused<<<(n + 79) / 80, 640, SMEM_K2B>>>(a01, ma12, w1, b1, gid, seg, n);

    // K3: readout
    readout_kernel<<<1, 128>>>(seg, wr1, br1, wr2, br2, wr3, br3, (float*)d_out);
}